// round 13
// baseline (speedup 1.0000x reference)
#include <cuda_runtime.h>
#include <cuda_bf16.h>
#include <cstdint>
#include <cstddef>

// ---------------------------------------------------------------------------
// Problem constants
// ---------------------------------------------------------------------------
#define HN   1024
#define SN   8192
#define TN   48
#define START_TAG 46
#define END_TAG   47
#define NEGV (-10000.0f)
#define POISON 0x7fc0deadu   // NaN payload; o*tanh(c) can never produce it

typedef unsigned long long u64;

// ---------------------------------------------------------------------------
// Scratch (device globals; no runtime allocation allowed)
// ---------------------------------------------------------------------------
__device__ float g_XI[2][SN][4 * HN];     // x@W_ih^T + biases (dir 1 in step order)
__device__ float g_Hseq[2][SN][HN];       // h sequences, dir 1 reversed to sentence order
__device__ float g_Hbuf[2][4][HN];        // [dir][slot][j]: 4-parity self-signaling h exchange
__device__ float g_feats[SN * TN];
__device__ unsigned char g_bp[SN * TN];
__device__ unsigned g_sink;               // spacer kernel sink

__device__ __forceinline__ uint4 ldacq4(const uint4* p) {
    uint4 v;
    asm volatile("ld.global.acquire.gpu.v4.u32 {%0,%1,%2,%3}, [%4];"
                 : "=r"(v.x), "=r"(v.y), "=r"(v.z), "=r"(v.w) : "l"(p));
    return v;
}
__device__ __forceinline__ void strel_f(float* p, float v) {
    asm volatile("st.global.release.gpu.b32 [%0], %1;"
                 :: "l"(p), "r"(__float_as_uint(v)) : "memory");
}
// f32x2 packed-FMA helpers (Blackwell 2x fp32 path; PTX-only)
__device__ __forceinline__ u64 ffma2(u64 a, u64 b, u64 c) {
    u64 d; asm("fma.rn.f32x2 %0, %1, %2, %3;" : "=l"(d) : "l"(a), "l"(b), "l"(c)); return d;
}
__device__ __forceinline__ u64 pack2(float lo, float hi) {
    u64 d; asm("mov.b64 %0, {%1, %2};" : "=l"(d) : "f"(lo), "f"(hi)); return d;
}
__device__ __forceinline__ void unpack2(u64 v, float& lo, float& hi) {
    asm("mov.b64 {%0, %1}, %2;" : "=f"(lo), "=f"(hi) : "l"(v));
}

// ---------------------------------------------------------------------------
// Init: slot 0 = zeros (h0 = 0), slots 1..3 = poison. Runs every launch.
// ---------------------------------------------------------------------------
__global__ void init_kernel() {
    int tid = threadIdx.x;
    unsigned* hb = (unsigned*)&g_Hbuf[0][0][0];
    for (int i = tid; i < 2 * 4 * HN; i += blockDim.x) {
        int slot = (i / HN) & 3;
        hb[i] = (slot == 0) ? 0u : POISON;
    }
}

// Spacer: shifts launch-slot indexing so ncu's fixed skip lands on lstm_kernel.
__global__ void spacer_kernel() {
    if (threadIdx.x == 0) g_sink = 1u;
}

// ---------------------------------------------------------------------------
// Kernel A: XI = x @ W_ih^T + (b_ih + b_hh)  for both directions.
// 128x128x16 tile, 256 threads, 8x8 microtile; inner product uses
// fma.rn.f32x2 (A-pairs reinterpreted from smem, B dup-packed per j).
// Numerical path validated in R5 (rel_err 0.0).
// ---------------------------------------------------------------------------
#define BM 128
#define BN 128
#define BK 16

__global__ void __launch_bounds__(256) xi_gemm_kernel(
    const float* __restrict__ x,
    const float* __restrict__ Wf, const float* __restrict__ Wb,
    const float* __restrict__ bihf, const float* __restrict__ bhhf,
    const float* __restrict__ bihb, const float* __restrict__ bhhb)
{
    __shared__ float As[BK][BM + 4];
    __shared__ float Bs[BK][BN + 4];

    const int z  = blockIdx.z;
    const float* W  = z ? Wb   : Wf;
    const float* b1 = z ? bihb : bihf;
    const float* b2 = z ? bhhb : bhhf;

    const int m0 = blockIdx.y * BM;
    const int n0 = blockIdx.x * BN;
    const int tid = threadIdx.x;

    const int lr = tid >> 2;          // 0..63
    const int lc = (tid & 3) << 2;    // 0,4,8,12
    const int ty = tid >> 4;          // 0..15
    const int tx = tid & 15;          // 0..15

    u64 acc[4][8];
#pragma unroll
    for (int i = 0; i < 4; i++)
#pragma unroll
        for (int j = 0; j < 8; j++) acc[i][j] = 0ull;

    for (int k0 = 0; k0 < HN; k0 += BK) {
        float4 va0 = *(const float4*)&x[(size_t)(m0 + lr)       * HN + k0 + lc];
        float4 va1 = *(const float4*)&x[(size_t)(m0 + lr + 64)  * HN + k0 + lc];
        float4 vb0 = *(const float4*)&W[(size_t)(n0 + lr)       * HN + k0 + lc];
        float4 vb1 = *(const float4*)&W[(size_t)(n0 + lr + 64)  * HN + k0 + lc];

        As[lc + 0][lr] = va0.x; As[lc + 1][lr] = va0.y; As[lc + 2][lr] = va0.z; As[lc + 3][lr] = va0.w;
        As[lc + 0][lr + 64] = va1.x; As[lc + 1][lr + 64] = va1.y; As[lc + 2][lr + 64] = va1.z; As[lc + 3][lr + 64] = va1.w;
        Bs[lc + 0][lr] = vb0.x; Bs[lc + 1][lr] = vb0.y; Bs[lc + 2][lr] = vb0.z; Bs[lc + 3][lr] = vb0.w;
        Bs[lc + 0][lr + 64] = vb1.x; Bs[lc + 1][lr + 64] = vb1.y; Bs[lc + 2][lr + 64] = vb1.z; Bs[lc + 3][lr + 64] = vb1.w;
        __syncthreads();

#pragma unroll
        for (int kk = 0; kk < BK; kk++) {
            u64 a01 = *(const u64*)&As[kk][ty * 8 + 0];
            u64 a23 = *(const u64*)&As[kk][ty * 8 + 2];
            u64 a45 = *(const u64*)&As[kk][ty * 8 + 4];
            u64 a67 = *(const u64*)&As[kk][ty * 8 + 6];
            float4 bA = *(const float4*)&Bs[kk][tx * 8];
            float4 bB = *(const float4*)&Bs[kk][tx * 8 + 4];
            float bs[8] = {bA.x, bA.y, bA.z, bA.w, bB.x, bB.y, bB.z, bB.w};
#pragma unroll
            for (int j = 0; j < 8; j++) {
                u64 bb = pack2(bs[j], bs[j]);
                acc[0][j] = ffma2(a01, bb, acc[0][j]);
                acc[1][j] = ffma2(a23, bb, acc[1][j]);
                acc[2][j] = ffma2(a45, bb, acc[2][j]);
                acc[3][j] = ffma2(a67, bb, acc[3][j]);
            }
        }
        __syncthreads();
    }

    // epilogue: unpack, add bias, vector store (reverse row for backward dir)
    float bias[8];
#pragma unroll
    for (int j = 0; j < 8; j++) {
        int n = n0 + tx * 8 + j;
        bias[j] = b1[n] + b2[n];
    }
#pragma unroll
    for (int i2 = 0; i2 < 4; i2++) {
        float rlo[8], rhi[8];
#pragma unroll
        for (int j = 0; j < 8; j++) unpack2(acc[i2][j], rlo[j], rhi[j]);
#pragma unroll
        for (int h = 0; h < 2; h++) {
            const float* r = h ? rhi : rlo;
            int m = m0 + ty * 8 + 2 * i2 + h;
            int row = z ? (SN - 1 - m) : m;
            float* outr = &g_XI[z][row][n0 + tx * 8];
            float4 v0, v1;
            v0.x = r[0] + bias[0]; v0.y = r[1] + bias[1]; v0.z = r[2] + bias[2]; v0.w = r[3] + bias[3];
            v1.x = r[4] + bias[4]; v1.y = r[5] + bias[5]; v1.z = r[6] + bias[6]; v1.w = r[7] + bias[7];
            *(float4*)outr = v0;
            *(float4*)(outr + 4) = v1;
        }
    }
}

// ---------------------------------------------------------------------------
// Kernel B: persistent BiLSTM recurrence — R12 exactly (R7 protocol, 5/3
// register/smem weight split, regs=254, block-synchronous gsum tail).
// ---------------------------------------------------------------------------
#define NBLK 128
#define OPB  16
#define LSTM_SMEM ((24 * 1024 + 1024 + 64) * 4)

__device__ __forceinline__ float sigf(float x) { return 1.0f / (1.0f + __expf(-x)); }

__global__ void __launch_bounds__(256, 1) lstm_kernel(
    const float* __restrict__ Whh_f, const float* __restrict__ Whh_b)
{
    extern __shared__ float sm[];
    float* wsh  = sm;                    // 24*1024 floats (smem-resident rows)
    float* hs   = sm + 24 * 1024;        // 1024 floats (h_prev)
    float* gsum = hs + 1024;             // 64 row sums

    const int tid  = threadIdx.x;
    const int w    = tid >> 5;
    const int lane = tid & 31;
    const int b    = blockIdx.x;
    const int dir  = b >> 6;
    const int jbase = (b & 63) * OPB;
    const float* Whh = dir ? Whh_b : Whh_f;

    // -------- load weights: rows 8w..8w+4 -> regs, 8w+5..8w+7 -> smem -------
    float4 wr[5][8];
#pragma unroll
    for (int q = 0; q < 5; q++) {
        int rr = 8 * w + q;
        int grow = (rr >> 4) * HN + jbase + (rr & 15);
        const float4* src = (const float4*)(Whh + (size_t)grow * HN);
#pragma unroll
        for (int m = 0; m < 8; m++) wr[q][m] = src[lane + 32 * m];
    }
#pragma unroll
    for (int q = 0; q < 3; q++) {
        int rr = 8 * w + 5 + q;
        int grow = (rr >> 4) * HN + jbase + (rr & 15);
        const float4* src = (const float4*)(Whh + (size_t)grow * HN);
        float4* dst = (float4*)(wsh + (size_t)(w * 3 + q) * HN);
#pragma unroll
        for (int m = 0; m < 8; m++) dst[lane + 32 * m] = src[lane + 32 * m];
    }

    float c_state = 0.0f;

    for (int t = 0; t < SN; t++) {
        // prefetch xi for this step (long-latency; hidden behind the poll)
        float xi0 = 0.f, xi1 = 0.f, xi2 = 0.f, xi3 = 0.f;
        if (tid < OPB) {
            const float* xr = &g_XI[dir][t][0];
            xi0 = __ldg(xr + 0 * HN + jbase + tid);
            xi1 = __ldg(xr + 1 * HN + jbase + tid);
            xi2 = __ldg(xr + 2 * HN + jbase + tid);
            xi3 = __ldg(xr + 3 * HN + jbase + tid);
        }

        // consume h_t: every thread polls its own 16B quad until valid,
        // then stages it straight into smem. Poll == load, no indirection.
        {
            const uint4* src = (const uint4*)&g_Hbuf[dir][t & 3][0] + tid;
            uint4 v;
            do {
                v = ldacq4(src);
            } while (v.x == POISON || v.y == POISON || v.z == POISON || v.w == POISON);
            ((uint4*)hs)[tid] = v;
        }
        __syncthreads();

        // poison our own chunk of slot (t+2)&3 (consumed; rewritten by us at
        // step t+1; release publish below orders this first).
        if (tid < OPB) {
            g_Hbuf[dir][(t + 2) & 3][jbase + tid] = __uint_as_float(POISON);
        }

        // h chunk into registers
        float4 hv[8];
#pragma unroll
        for (int m = 0; m < 8; m++) hv[m] = ((const float4*)hs)[lane + 32 * m];

        float acc[8];
#pragma unroll
        for (int r = 0; r < 8; r++) acc[r] = 0.0f;

        // register-resident rows (5)
#pragma unroll
        for (int q = 0; q < 5; q++) {
#pragma unroll
            for (int m = 0; m < 8; m++) {
                float4 ww = wr[q][m];
                acc[q] += ww.x * hv[m].x + ww.y * hv[m].y + ww.z * hv[m].z + ww.w * hv[m].w;
            }
        }
        // smem-resident rows (3)
#pragma unroll
        for (int q = 0; q < 3; q++) {
            const float4* wp = (const float4*)(wsh + (size_t)(w * 3 + q) * HN);
            float a = 0.0f;
#pragma unroll
            for (int m = 0; m < 8; m++) {
                float4 ww = wp[lane + 32 * m];
                a += ww.x * hv[m].x + ww.y * hv[m].y + ww.z * hv[m].z + ww.w * hv[m].w;
            }
            acc[5 + q] = a;
        }

        // warp reduction over K
#pragma unroll
        for (int r = 0; r < 8; r++) {
#pragma unroll
            for (int o = 16; o > 0; o >>= 1)
                acc[r] += __shfl_xor_sync(0xffffffffu, acc[r], o);
        }
        if (lane == 0) {
#pragma unroll
            for (int r = 0; r < 8; r++) gsum[8 * w + r] = acc[r];
        }
        __syncthreads();

        // gate assembly + cell update + publish h_{t+1} (coherent burst)
        if (tid < OPB) {
            float gi = gsum[tid]          + xi0;
            float gf = gsum[16 + tid]     + xi1;
            float gg = gsum[32 + tid]     + xi2;
            float go = gsum[48 + tid]     + xi3;
            float si = sigf(gi);
            float sf = sigf(gf);
            float tg = tanhf(gg);
            float so = sigf(go);
            c_state = sf * c_state + si * tg;
            float hout = so * tanhf(c_state);
            int j = jbase + tid;
            strel_f(&g_Hbuf[dir][(t + 1) & 3][j], hout);
            int srow = dir ? (SN - 1 - t) : t;
            g_Hseq[dir][srow][j] = hout;
        }
    }
}

// ---------------------------------------------------------------------------
// Kernel C: feats = concat(hf, hb) @ W_dense^T + b_dense. 4 rows per block.
// ---------------------------------------------------------------------------
__global__ void __launch_bounds__(256) dense_kernel(
    const float* __restrict__ Wd, const float* __restrict__ bd)
{
    __shared__ float hsm[4][2 * HN];
    const int tid  = threadIdx.x;
    const int w    = tid >> 5;
    const int lane = tid & 31;
    const int s0   = blockIdx.x * 4;

    for (int i = tid; i < 4 * 512; i += 256) {
        int r = i >> 9, f4 = i & 511;
        float4 v;
        if (f4 < 256) v = *(const float4*)&g_Hseq[0][s0 + r][f4 * 4];
        else          v = *(const float4*)&g_Hseq[1][s0 + r][(f4 - 256) * 4];
        *(float4*)&hsm[r][f4 * 4] = v;
    }
    __syncthreads();

    for (int idx = w; idx < 4 * TN; idx += 8) {
        int r = idx / TN, tag = idx - r * TN;
        const float4* wrow = (const float4*)(Wd + (size_t)tag * 2 * HN);
        const float4* hrow = (const float4*)&hsm[r][0];
        float acc = 0.0f;
#pragma unroll
        for (int m = 0; m < 16; m++) {
            float4 a  = wrow[lane + 32 * m];
            float4 h4 = hrow[lane + 32 * m];
            acc += a.x * h4.x + a.y * h4.y + a.z * h4.z + a.w * h4.w;
        }
#pragma unroll
        for (int o = 16; o > 0; o >>= 1) acc += __shfl_xor_sync(0xffffffffu, acc, o);
        if (lane == 0) g_feats[(s0 + r) * TN + tag] = acc + __ldg(&bd[tag]);
    }
}

// ---------------------------------------------------------------------------
// Kernel D: Viterbi forward + chunked smem backtrack (validated).
// 2 threads per tag row, 4 compare chains each; first-max tie-break preserved.
// ---------------------------------------------------------------------------
__global__ void __launch_bounds__(128) viterbi_kernel(
    const float* __restrict__ trans, float* __restrict__ out, int out_size)
{
    __shared__ float fvb[2][TN];
    __shared__ unsigned char bpc[256 * TN];   // 12 KB backtrack chunk
    const int tid  = threadIdx.x;
    const int row  = tid >> 1;
    const int half = tid & 1;

    float tr[24];
    if (tid < 96) {
#pragma unroll
        for (int j = 0; j < 24; j++) tr[j] = __ldg(&trans[row * TN + half * 24 + j]);
    }
    if (tid < TN) fvb[0][tid] = (tid == START_TAG) ? 0.0f : NEGV;
    __syncthreads();

    for (int s = 0; s < SN; s++) {
        const float* fv = fvb[s & 1];
        float* fvn = fvb[(s + 1) & 1];
        if (tid < 96) {
            float feat = half ? 0.0f : __ldg(&g_feats[s * TN + row]);
            const int jb = half * 24;
            float b0 = fv[jb + 0]  + tr[0];  int a0 = jb + 0;
            float b1 = fv[jb + 6]  + tr[6];  int a1 = jb + 6;
            float b2 = fv[jb + 12] + tr[12]; int a2 = jb + 12;
            float b3 = fv[jb + 18] + tr[18]; int a3 = jb + 18;
#pragma unroll
            for (int k = 1; k < 6; k++) {
                float v0 = fv[jb + k]      + tr[k];      if (v0 > b0) { b0 = v0; a0 = jb + k; }
                float v1 = fv[jb + 6 + k]  + tr[6 + k];  if (v1 > b1) { b1 = v1; a1 = jb + 6 + k; }
                float v2 = fv[jb + 12 + k] + tr[12 + k]; if (v2 > b2) { b2 = v2; a2 = jb + 12 + k; }
                float v3 = fv[jb + 18 + k] + tr[18 + k]; if (v3 > b3) { b3 = v3; a3 = jb + 18 + k; }
            }
            if (b1 > b0) { b0 = b1; a0 = a1; }
            if (b3 > b2) { b2 = b3; a2 = a3; }
            if (b2 > b0) { b0 = b2; a0 = a2; }
            float bo = __shfl_xor_sync(0xffffffffu, b0, 1);
            int   ao = __shfl_xor_sync(0xffffffffu, a0, 1);
            if (half == 0) {
                if (bo > b0) { b0 = bo; a0 = ao; }  // other half's indices all larger
                fvn[row] = b0 + feat;
                g_bp[s * TN + row] = (unsigned char)a0;
            }
        }
        __syncthreads();
    }

    __shared__ int s_arg;
    if (tid == 0) {
        float best = -3.4e38f; int arg = 0;
        const float* fvf = fvb[SN & 1];
        for (int i = 0; i < TN; i++) {
            float v = fvf[i] + __ldg(&trans[END_TAG * TN + i]);
            if (v > best) { best = v; arg = i; }
        }
        if (out_size > 0) out[0] = best;
        if (SN < out_size) out[SN] = (float)arg;
        s_arg = arg;
    }
    __syncthreads();

    int cur = s_arg;  // live in tid 0 only
    for (int c0 = SN - 256; c0 >= 0; c0 -= 256) {
        const uint4* src = (const uint4*)&g_bp[c0 * TN];
        uint4* dst = (uint4*)bpc;
        for (int i = tid; i < 256 * TN / 16; i += 128) dst[i] = src[i];
        __syncthreads();
        if (tid == 0) {
            int hi = c0 + 255; if (hi > SN - 1) hi = SN - 1;
            int lo = (c0 > 0) ? c0 : 1;
            for (int s = hi; s >= lo; s--) {
                cur = bpc[(s - c0) * TN + cur];
                if (s < out_size) out[s] = (float)cur;
            }
        }
        __syncthreads();
    }
}

// ---------------------------------------------------------------------------
// Launch
// ---------------------------------------------------------------------------
extern "C" void kernel_launch(void* const* d_in, const int* in_sizes, int n_in,
                              void* d_out, int out_size)
{
    const float* sentence    = (const float*)d_in[0];
    const float* W_ih_f      = (const float*)d_in[1];
    const float* W_hh_f      = (const float*)d_in[2];
    const float* b_ih_f      = (const float*)d_in[3];
    const float* b_hh_f      = (const float*)d_in[4];
    const float* W_ih_b      = (const float*)d_in[5];
    const float* W_hh_b      = (const float*)d_in[6];
    const float* b_ih_b      = (const float*)d_in[7];
    const float* b_hh_b      = (const float*)d_in[8];
    const float* W_dense     = (const float*)d_in[9];
    const float* b_dense     = (const float*)d_in[10];
    const float* transitions = (const float*)d_in[11];
    float* out = (float*)d_out;

    (void)in_sizes; (void)n_in;

    cudaFuncSetAttribute(lstm_kernel, cudaFuncAttributeMaxDynamicSharedMemorySize, LSTM_SMEM);

    init_kernel<<<1, 256>>>();

    dim3 ggemm(4 * HN / BN, SN / BM, 2);
    xi_gemm_kernel<<<ggemm, 256>>>(sentence, W_ih_f, W_ih_b,
                                   b_ih_f, b_hh_f, b_ih_b, b_hh_b);

    spacer_kernel<<<1, 32>>>();   // keeps ncu's fixed skip landing on lstm

    lstm_kernel<<<NBLK, 256, LSTM_SMEM>>>(W_hh_f, W_hh_b);

    dense_kernel<<<SN / 4, 256>>>(W_dense, b_dense);

    viterbi_kernel<<<1, 128>>>(transitions, out, out_size);
}

// round 14
// speedup vs baseline: 1.0113x; 1.0113x over previous
#include <cuda_runtime.h>
#include <cuda_bf16.h>
#include <cstdint>
#include <cstddef>

// ---------------------------------------------------------------------------
// Problem constants
// ---------------------------------------------------------------------------
#define HN   1024
#define SN   8192
#define TN   48
#define START_TAG 46
#define END_TAG   47
#define NEGV (-10000.0f)
#define POISON 0x7fc0deadu   // NaN payload; o*tanh(c) can never produce it

// ---------------------------------------------------------------------------
// Scratch (device globals; no runtime allocation allowed)
// ---------------------------------------------------------------------------
__device__ float g_XI[2][SN][4 * HN];     // x@W_ih^T + biases (dir 1 in step order)
__device__ float g_Hseq[2][SN][HN];       // h sequences, dir 1 reversed to sentence order
__device__ float g_Hbuf[2][4][HN];        // [dir][slot][j]: 4-parity self-signaling h exchange
__device__ float g_feats[SN * TN];
__device__ unsigned char g_bp[SN * TN];
__device__ unsigned g_sink;               // spacer kernel sink

__device__ __forceinline__ uint4 ldacq4(const uint4* p) {
    uint4 v;
    asm volatile("ld.global.acquire.gpu.v4.u32 {%0,%1,%2,%3}, [%4];"
                 : "=r"(v.x), "=r"(v.y), "=r"(v.z), "=r"(v.w) : "l"(p));
    return v;
}
__device__ __forceinline__ void strel_f(float* p, float v) {
    asm volatile("st.global.release.gpu.b32 [%0], %1;"
                 :: "l"(p), "r"(__float_as_uint(v)) : "memory");
}

// ---------------------------------------------------------------------------
// Init: slot 0 = zeros (h0 = 0), slots 1..3 = poison. Runs every launch.
// ---------------------------------------------------------------------------
__global__ void init_kernel() {
    int tid = threadIdx.x;
    unsigned* hb = (unsigned*)&g_Hbuf[0][0][0];
    for (int i = tid; i < 2 * 4 * HN; i += blockDim.x) {
        int slot = (i / HN) & 3;
        hb[i] = (slot == 0) ? 0u : POISON;
    }
}

// Spacer: shifts launch-slot indexing so ncu's fixed skip lands on lstm_kernel.
__global__ void spacer_kernel() {
    if (threadIdx.x == 0) g_sink = 1u;
}

// ---------------------------------------------------------------------------
// Kernel A: XI = x @ W_ih^T + (b_ih + b_hh)  for both directions.
// 128x128x16 tile, 256 threads, 8x8 microtile, plain FFMA (R12 math),
// NOW with ping-pong smem double buffering: prefetch next k-tile into
// registers during compute, ONE __syncthreads per k-iteration.
// ---------------------------------------------------------------------------
#define BM 128
#define BN 128
#define BK 16

__global__ void __launch_bounds__(256, 2) xi_gemm_kernel(
    const float* __restrict__ x,
    const float* __restrict__ Wf, const float* __restrict__ Wb,
    const float* __restrict__ bihf, const float* __restrict__ bhhf,
    const float* __restrict__ bihb, const float* __restrict__ bhhb)
{
    __shared__ float As[2][BK][BM + 4];
    __shared__ float Bs[2][BK][BN + 4];

    const int z  = blockIdx.z;
    const float* W  = z ? Wb   : Wf;
    const float* b1 = z ? bihb : bihf;
    const float* b2 = z ? bhhb : bhhf;

    const int m0 = blockIdx.y * BM;
    const int n0 = blockIdx.x * BN;
    const int tid = threadIdx.x;

    const int lr = tid >> 2;          // 0..63
    const int lc = (tid & 3) << 2;    // 0,4,8,12
    const int ty = tid >> 4;          // 0..15
    const int tx = tid & 15;          // 0..15

    const float* A0 = x + (size_t)(m0 + lr)      * HN + lc;
    const float* A1 = x + (size_t)(m0 + lr + 64) * HN + lc;
    const float* B0 = W + (size_t)(n0 + lr)      * HN + lc;
    const float* B1 = W + (size_t)(n0 + lr + 64) * HN + lc;

    // prologue: tile k=0 -> buffer 0
    {
        float4 va0 = *(const float4*)A0;
        float4 va1 = *(const float4*)A1;
        float4 vb0 = *(const float4*)B0;
        float4 vb1 = *(const float4*)B1;
        As[0][lc + 0][lr] = va0.x; As[0][lc + 1][lr] = va0.y; As[0][lc + 2][lr] = va0.z; As[0][lc + 3][lr] = va0.w;
        As[0][lc + 0][lr + 64] = va1.x; As[0][lc + 1][lr + 64] = va1.y; As[0][lc + 2][lr + 64] = va1.z; As[0][lc + 3][lr + 64] = va1.w;
        Bs[0][lc + 0][lr] = vb0.x; Bs[0][lc + 1][lr] = vb0.y; Bs[0][lc + 2][lr] = vb0.z; Bs[0][lc + 3][lr] = vb0.w;
        Bs[0][lc + 0][lr + 64] = vb1.x; Bs[0][lc + 1][lr + 64] = vb1.y; Bs[0][lc + 2][lr + 64] = vb1.z; Bs[0][lc + 3][lr + 64] = vb1.w;
    }
    __syncthreads();

    float acc[8][8];
#pragma unroll
    for (int i = 0; i < 8; i++)
#pragma unroll
        for (int j = 0; j < 8; j++) acc[i][j] = 0.0f;

    int cur = 0;
    for (int k0 = 0; k0 < HN; k0 += BK) {
        const bool more = (k0 + BK) < HN;
        float4 na0, na1, nb0, nb1;
        if (more) {                      // prefetch next tile (overlaps compute)
            na0 = *(const float4*)(A0 + k0 + BK);
            na1 = *(const float4*)(A1 + k0 + BK);
            nb0 = *(const float4*)(B0 + k0 + BK);
            nb1 = *(const float4*)(B1 + k0 + BK);
        }

#pragma unroll
        for (int kk = 0; kk < BK; kk++) {
            float a[8], b[8];
            *(float4*)&a[0] = *(const float4*)&As[cur][kk][ty * 8];
            *(float4*)&a[4] = *(const float4*)&As[cur][kk][ty * 8 + 4];
            *(float4*)&b[0] = *(const float4*)&Bs[cur][kk][tx * 8];
            *(float4*)&b[4] = *(const float4*)&Bs[cur][kk][tx * 8 + 4];
#pragma unroll
            for (int i = 0; i < 8; i++)
#pragma unroll
                for (int j = 0; j < 8; j++) acc[i][j] += a[i] * b[j];
        }

        if (more) {
            const int nxt = cur ^ 1;
            As[nxt][lc + 0][lr] = na0.x; As[nxt][lc + 1][lr] = na0.y; As[nxt][lc + 2][lr] = na0.z; As[nxt][lc + 3][lr] = na0.w;
            As[nxt][lc + 0][lr + 64] = na1.x; As[nxt][lc + 1][lr + 64] = na1.y; As[nxt][lc + 2][lr + 64] = na1.z; As[nxt][lc + 3][lr + 64] = na1.w;
            Bs[nxt][lc + 0][lr] = nb0.x; Bs[nxt][lc + 1][lr] = nb0.y; Bs[nxt][lc + 2][lr] = nb0.z; Bs[nxt][lc + 3][lr] = nb0.w;
            Bs[nxt][lc + 0][lr + 64] = nb1.x; Bs[nxt][lc + 1][lr + 64] = nb1.y; Bs[nxt][lc + 2][lr + 64] = nb1.z; Bs[nxt][lc + 3][lr + 64] = nb1.w;
            __syncthreads();
            cur = nxt;
        }
    }

    float bias[8];
#pragma unroll
    for (int j = 0; j < 8; j++) {
        int n = n0 + tx * 8 + j;
        bias[j] = b1[n] + b2[n];
    }
#pragma unroll
    for (int i = 0; i < 8; i++) {
        int m = m0 + ty * 8 + i;
        int row = z ? (SN - 1 - m) : m;
        float* outr = &g_XI[z][row][n0 + tx * 8];
        float4 v0, v1;
        v0.x = acc[i][0] + bias[0]; v0.y = acc[i][1] + bias[1];
        v0.z = acc[i][2] + bias[2]; v0.w = acc[i][3] + bias[3];
        v1.x = acc[i][4] + bias[4]; v1.y = acc[i][5] + bias[5];
        v1.z = acc[i][6] + bias[6]; v1.w = acc[i][7] + bias[7];
        *(float4*)outr = v0;
        *(float4*)(outr + 4) = v1;
    }
}

// ---------------------------------------------------------------------------
// Kernel B: persistent BiLSTM recurrence — R12 exactly (R7 protocol, 5/3
// register/smem weight split, regs=254, block-synchronous gsum tail).
// ---------------------------------------------------------------------------
#define NBLK 128
#define OPB  16
#define LSTM_SMEM ((24 * 1024 + 1024 + 64) * 4)

__device__ __forceinline__ float sigf(float x) { return 1.0f / (1.0f + __expf(-x)); }

__global__ void __launch_bounds__(256, 1) lstm_kernel(
    const float* __restrict__ Whh_f, const float* __restrict__ Whh_b)
{
    extern __shared__ float sm[];
    float* wsh  = sm;                    // 24*1024 floats (smem-resident rows)
    float* hs   = sm + 24 * 1024;        // 1024 floats (h_prev)
    float* gsum = hs + 1024;             // 64 row sums

    const int tid  = threadIdx.x;
    const int w    = tid >> 5;
    const int lane = tid & 31;
    const int b    = blockIdx.x;
    const int dir  = b >> 6;
    const int jbase = (b & 63) * OPB;
    const float* Whh = dir ? Whh_b : Whh_f;

    // -------- load weights: rows 8w..8w+4 -> regs, 8w+5..8w+7 -> smem -------
    float4 wr[5][8];
#pragma unroll
    for (int q = 0; q < 5; q++) {
        int rr = 8 * w + q;
        int grow = (rr >> 4) * HN + jbase + (rr & 15);
        const float4* src = (const float4*)(Whh + (size_t)grow * HN);
#pragma unroll
        for (int m = 0; m < 8; m++) wr[q][m] = src[lane + 32 * m];
    }
#pragma unroll
    for (int q = 0; q < 3; q++) {
        int rr = 8 * w + 5 + q;
        int grow = (rr >> 4) * HN + jbase + (rr & 15);
        const float4* src = (const float4*)(Whh + (size_t)grow * HN);
        float4* dst = (float4*)(wsh + (size_t)(w * 3 + q) * HN);
#pragma unroll
        for (int m = 0; m < 8; m++) dst[lane + 32 * m] = src[lane + 32 * m];
    }

    float c_state = 0.0f;

    for (int t = 0; t < SN; t++) {
        // prefetch xi for this step (long-latency; hidden behind the poll)
        float xi0 = 0.f, xi1 = 0.f, xi2 = 0.f, xi3 = 0.f;
        if (tid < OPB) {
            const float* xr = &g_XI[dir][t][0];
            xi0 = __ldg(xr + 0 * HN + jbase + tid);
            xi1 = __ldg(xr + 1 * HN + jbase + tid);
            xi2 = __ldg(xr + 2 * HN + jbase + tid);
            xi3 = __ldg(xr + 3 * HN + jbase + tid);
        }

        // consume h_t: every thread polls its own 16B quad until valid,
        // then stages it straight into smem. Poll == load, no indirection.
        {
            const uint4* src = (const uint4*)&g_Hbuf[dir][t & 3][0] + tid;
            uint4 v;
            do {
                v = ldacq4(src);
            } while (v.x == POISON || v.y == POISON || v.z == POISON || v.w == POISON);
            ((uint4*)hs)[tid] = v;
        }
        __syncthreads();

        // poison our own chunk of slot (t+2)&3 (consumed; rewritten by us at
        // step t+1; release publish below orders this first).
        if (tid < OPB) {
            g_Hbuf[dir][(t + 2) & 3][jbase + tid] = __uint_as_float(POISON);
        }

        // h chunk into registers
        float4 hv[8];
#pragma unroll
        for (int m = 0; m < 8; m++) hv[m] = ((const float4*)hs)[lane + 32 * m];

        float acc[8];
#pragma unroll
        for (int r = 0; r < 8; r++) acc[r] = 0.0f;

        // register-resident rows (5)
#pragma unroll
        for (int q = 0; q < 5; q++) {
#pragma unroll
            for (int m = 0; m < 8; m++) {
                float4 ww = wr[q][m];
                acc[q] += ww.x * hv[m].x + ww.y * hv[m].y + ww.z * hv[m].z + ww.w * hv[m].w;
            }
        }
        // smem-resident rows (3)
#pragma unroll
        for (int q = 0; q < 3; q++) {
            const float4* wp = (const float4*)(wsh + (size_t)(w * 3 + q) * HN);
            float a = 0.0f;
#pragma unroll
            for (int m = 0; m < 8; m++) {
                float4 ww = wp[lane + 32 * m];
                a += ww.x * hv[m].x + ww.y * hv[m].y + ww.z * hv[m].z + ww.w * hv[m].w;
            }
            acc[5 + q] = a;
        }

        // warp reduction over K
#pragma unroll
        for (int r = 0; r < 8; r++) {
#pragma unroll
            for (int o = 16; o > 0; o >>= 1)
                acc[r] += __shfl_xor_sync(0xffffffffu, acc[r], o);
        }
        if (lane == 0) {
#pragma unroll
            for (int r = 0; r < 8; r++) gsum[8 * w + r] = acc[r];
        }
        __syncthreads();

        // gate assembly + cell update + publish h_{t+1} (coherent burst)
        if (tid < OPB) {
            float gi = gsum[tid]          + xi0;
            float gf = gsum[16 + tid]     + xi1;
            float gg = gsum[32 + tid]     + xi2;
            float go = gsum[48 + tid]     + xi3;
            float si = sigf(gi);
            float sf = sigf(gf);
            float tg = tanhf(gg);
            float so = sigf(go);
            c_state = sf * c_state + si * tg;
            float hout = so * tanhf(c_state);
            int j = jbase + tid;
            strel_f(&g_Hbuf[dir][(t + 1) & 3][j], hout);
            int srow = dir ? (SN - 1 - t) : t;
            g_Hseq[dir][srow][j] = hout;
        }
    }
}

// ---------------------------------------------------------------------------
// Kernel C: feats = concat(hf, hb) @ W_dense^T + b_dense. 4 rows per block.
// ---------------------------------------------------------------------------
__global__ void __launch_bounds__(256) dense_kernel(
    const float* __restrict__ Wd, const float* __restrict__ bd)
{
    __shared__ float hsm[4][2 * HN];
    const int tid  = threadIdx.x;
    const int w    = tid >> 5;
    const int lane = tid & 31;
    const int s0   = blockIdx.x * 4;

    for (int i = tid; i < 4 * 512; i += 256) {
        int r = i >> 9, f4 = i & 511;
        float4 v;
        if (f4 < 256) v = *(const float4*)&g_Hseq[0][s0 + r][f4 * 4];
        else          v = *(const float4*)&g_Hseq[1][s0 + r][(f4 - 256) * 4];
        *(float4*)&hsm[r][f4 * 4] = v;
    }
    __syncthreads();

    for (int idx = w; idx < 4 * TN; idx += 8) {
        int r = idx / TN, tag = idx - r * TN;
        const float4* wrow = (const float4*)(Wd + (size_t)tag * 2 * HN);
        const float4* hrow = (const float4*)&hsm[r][0];
        float acc = 0.0f;
#pragma unroll
        for (int m = 0; m < 16; m++) {
            float4 a  = wrow[lane + 32 * m];
            float4 h4 = hrow[lane + 32 * m];
            acc += a.x * h4.x + a.y * h4.y + a.z * h4.z + a.w * h4.w;
        }
#pragma unroll
        for (int o = 16; o > 0; o >>= 1) acc += __shfl_xor_sync(0xffffffffu, acc, o);
        if (lane == 0) g_feats[(s0 + r) * TN + tag] = acc + __ldg(&bd[tag]);
    }
}

// ---------------------------------------------------------------------------
// Kernel D: Viterbi forward + chunked smem backtrack (validated).
// 2 threads per tag row, 4 compare chains each; first-max tie-break preserved.
// ---------------------------------------------------------------------------
__global__ void __launch_bounds__(128) viterbi_kernel(
    const float* __restrict__ trans, float* __restrict__ out, int out_size)
{
    __shared__ float fvb[2][TN];
    __shared__ unsigned char bpc[256 * TN];   // 12 KB backtrack chunk
    const int tid  = threadIdx.x;
    const int row  = tid >> 1;
    const int half = tid & 1;

    float tr[24];
    if (tid < 96) {
#pragma unroll
        for (int j = 0; j < 24; j++) tr[j] = __ldg(&trans[row * TN + half * 24 + j]);
    }
    if (tid < TN) fvb[0][tid] = (tid == START_TAG) ? 0.0f : NEGV;
    __syncthreads();

    for (int s = 0; s < SN; s++) {
        const float* fv = fvb[s & 1];
        float* fvn = fvb[(s + 1) & 1];
        if (tid < 96) {
            float feat = half ? 0.0f : __ldg(&g_feats[s * TN + row]);
            const int jb = half * 24;
            float b0 = fv[jb + 0]  + tr[0];  int a0 = jb + 0;
            float b1 = fv[jb + 6]  + tr[6];  int a1 = jb + 6;
            float b2 = fv[jb + 12] + tr[12]; int a2 = jb + 12;
            float b3 = fv[jb + 18] + tr[18]; int a3 = jb + 18;
#pragma unroll
            for (int k = 1; k < 6; k++) {
                float v0 = fv[jb + k]      + tr[k];      if (v0 > b0) { b0 = v0; a0 = jb + k; }
                float v1 = fv[jb + 6 + k]  + tr[6 + k];  if (v1 > b1) { b1 = v1; a1 = jb + 6 + k; }
                float v2 = fv[jb + 12 + k] + tr[12 + k]; if (v2 > b2) { b2 = v2; a2 = jb + 12 + k; }
                float v3 = fv[jb + 18 + k] + tr[18 + k]; if (v3 > b3) { b3 = v3; a3 = jb + 18 + k; }
            }
            if (b1 > b0) { b0 = b1; a0 = a1; }
            if (b3 > b2) { b2 = b3; a2 = a3; }
            if (b2 > b0) { b0 = b2; a0 = a2; }
            float bo = __shfl_xor_sync(0xffffffffu, b0, 1);
            int   ao = __shfl_xor_sync(0xffffffffu, a0, 1);
            if (half == 0) {
                if (bo > b0) { b0 = bo; a0 = ao; }  // other half's indices all larger
                fvn[row] = b0 + feat;
                g_bp[s * TN + row] = (unsigned char)a0;
            }
        }
        __syncthreads();
    }

    __shared__ int s_arg;
    if (tid == 0) {
        float best = -3.4e38f; int arg = 0;
        const float* fvf = fvb[SN & 1];
        for (int i = 0; i < TN; i++) {
            float v = fvf[i] + __ldg(&trans[END_TAG * TN + i]);
            if (v > best) { best = v; arg = i; }
        }
        if (out_size > 0) out[0] = best;
        if (SN < out_size) out[SN] = (float)arg;
        s_arg = arg;
    }
    __syncthreads();

    int cur = s_arg;  // live in tid 0 only
    for (int c0 = SN - 256; c0 >= 0; c0 -= 256) {
        const uint4* src = (const uint4*)&g_bp[c0 * TN];
        uint4* dst = (uint4*)bpc;
        for (int i = tid; i < 256 * TN / 16; i += 128) dst[i] = src[i];
        __syncthreads();
        if (tid == 0) {
            int hi = c0 + 255; if (hi > SN - 1) hi = SN - 1;
            int lo = (c0 > 0) ? c0 : 1;
            for (int s = hi; s >= lo; s--) {
                cur = bpc[(s - c0) * TN + cur];
                if (s < out_size) out[s] = (float)cur;
            }
        }
        __syncthreads();
    }
}

// ---------------------------------------------------------------------------
// Launch
// ---------------------------------------------------------------------------
extern "C" void kernel_launch(void* const* d_in, const int* in_sizes, int n_in,
                              void* d_out, int out_size)
{
    const float* sentence    = (const float*)d_in[0];
    const float* W_ih_f      = (const float*)d_in[1];
    const float* W_hh_f      = (const float*)d_in[2];
    const float* b_ih_f      = (const float*)d_in[3];
    const float* b_hh_f      = (const float*)d_in[4];
    const float* W_ih_b      = (const float*)d_in[5];
    const float* W_hh_b      = (const float*)d_in[6];
    const float* b_ih_b      = (const float*)d_in[7];
    const float* b_hh_b      = (const float*)d_in[8];
    const float* W_dense     = (const float*)d_in[9];
    const float* b_dense     = (const float*)d_in[10];
    const float* transitions = (const float*)d_in[11];
    float* out = (float*)d_out;

    (void)in_sizes; (void)n_in;

    cudaFuncSetAttribute(lstm_kernel, cudaFuncAttributeMaxDynamicSharedMemorySize, LSTM_SMEM);

    init_kernel<<<1, 256>>>();

    dim3 ggemm(4 * HN / BN, SN / BM, 2);
    xi_gemm_kernel<<<ggemm, 256>>>(sentence, W_ih_f, W_ih_b,
                                   b_ih_f, b_hh_f, b_ih_b, b_hh_b);

    spacer_kernel<<<1, 32>>>();   // keeps ncu's fixed skip landing on lstm

    lstm_kernel<<<NBLK, 256, LSTM_SMEM>>>(W_hh_f, W_hh_b);

    dense_kernel<<<SN / 4, 256>>>(W_dense, b_dense);

    viterbi_kernel<<<1, 128>>>(transitions, out, out_size);
}

// round 15
// speedup vs baseline: 1.0749x; 1.0629x over previous
#include <cuda_runtime.h>
#include <cuda_bf16.h>
#include <cstdint>
#include <cstddef>

// ---------------------------------------------------------------------------
// Problem constants
// ---------------------------------------------------------------------------
#define HN   1024
#define SN   8192
#define TN   48
#define START_TAG 46
#define END_TAG   47
#define NEGV (-10000.0f)
#define POISON 0x7fc0deadu   // NaN payload; o*tanh(c) can never produce it

// ---------------------------------------------------------------------------
// Scratch (device globals; no runtime allocation allowed)
// ---------------------------------------------------------------------------
__device__ float g_XI[2][SN][4 * HN];     // x@W_ih^T + biases (dir 1 in step order)
__device__ float g_Hseq[2][SN][HN];       // h sequences, dir 1 reversed to sentence order
__device__ float g_Hbuf[2][4][HN];        // [dir][slot][j]: 4-parity self-signaling h exchange
__device__ float g_feats[SN * TN];
__device__ unsigned char g_bp[SN * TN];
__device__ unsigned g_sink;               // spacer kernel sink

__device__ __forceinline__ uint4 ldacq4(const uint4* p) {
    uint4 v;
    asm volatile("ld.global.acquire.gpu.v4.u32 {%0,%1,%2,%3}, [%4];"
                 : "=r"(v.x), "=r"(v.y), "=r"(v.z), "=r"(v.w) : "l"(p));
    return v;
}
__device__ __forceinline__ void strel_f(float* p, float v) {
    asm volatile("st.global.release.gpu.b32 [%0], %1;"
                 :: "l"(p), "r"(__float_as_uint(v)) : "memory");
}
// HW tanh (sm_75+): MUFU-class, lat ~16, max abs err ~1e-5.
__device__ __forceinline__ float tanh_hw(float x) {
    float y; asm("tanh.approx.f32 %0, %1;" : "=f"(y) : "f"(x)); return y;
}
// sigmoid via HW tanh: sig(x) = 0.5*tanh(x/2) + 0.5  (one MUFU + 2 FMA,
// replaces __expf + IEEE divide on the publish critical path)
__device__ __forceinline__ float sig_hw(float x) {
    return fmaf(0.5f, tanh_hw(0.5f * x), 0.5f);
}

// ---------------------------------------------------------------------------
// Init: slot 0 = zeros (h0 = 0), slots 1..3 = poison. Runs every launch.
// ---------------------------------------------------------------------------
__global__ void init_kernel() {
    int tid = threadIdx.x;
    unsigned* hb = (unsigned*)&g_Hbuf[0][0][0];
    for (int i = tid; i < 2 * 4 * HN; i += blockDim.x) {
        int slot = (i / HN) & 3;
        hb[i] = (slot == 0) ? 0u : POISON;
    }
}

// Spacer: shifts launch-slot indexing so ncu's fixed skip lands on lstm_kernel.
__global__ void spacer_kernel() {
    if (threadIdx.x == 0) g_sink = 1u;
}

// ---------------------------------------------------------------------------
// Kernel A: XI = x @ W_ih^T + (b_ih + b_hh)  for both directions.
// Tiled SGEMM: BM=BN=128, BK=16, 256 threads, 8x8 microtile.
// R12 plain-FFMA form (f32x2 and double-buffer variants both regressed).
// ---------------------------------------------------------------------------
#define BM 128
#define BN 128
#define BK 16

__global__ void __launch_bounds__(256) xi_gemm_kernel(
    const float* __restrict__ x,
    const float* __restrict__ Wf, const float* __restrict__ Wb,
    const float* __restrict__ bihf, const float* __restrict__ bhhf,
    const float* __restrict__ bihb, const float* __restrict__ bhhb)
{
    __shared__ float As[BK][BM + 4];
    __shared__ float Bs[BK][BN + 4];

    const int z  = blockIdx.z;
    const float* W  = z ? Wb   : Wf;
    const float* b1 = z ? bihb : bihf;
    const float* b2 = z ? bhhb : bhhf;

    const int m0 = blockIdx.y * BM;
    const int n0 = blockIdx.x * BN;
    const int tid = threadIdx.x;

    const int lr = tid >> 2;          // 0..63
    const int lc = (tid & 3) << 2;    // 0,4,8,12
    const int ty = tid >> 4;          // 0..15
    const int tx = tid & 15;          // 0..15

    float acc[8][8];
#pragma unroll
    for (int i = 0; i < 8; i++)
#pragma unroll
        for (int j = 0; j < 8; j++) acc[i][j] = 0.0f;

    for (int k0 = 0; k0 < HN; k0 += BK) {
        float4 va0 = *(const float4*)&x[(size_t)(m0 + lr)       * HN + k0 + lc];
        float4 va1 = *(const float4*)&x[(size_t)(m0 + lr + 64)  * HN + k0 + lc];
        float4 vb0 = *(const float4*)&W[(size_t)(n0 + lr)       * HN + k0 + lc];
        float4 vb1 = *(const float4*)&W[(size_t)(n0 + lr + 64)  * HN + k0 + lc];

        As[lc + 0][lr] = va0.x; As[lc + 1][lr] = va0.y; As[lc + 2][lr] = va0.z; As[lc + 3][lr] = va0.w;
        As[lc + 0][lr + 64] = va1.x; As[lc + 1][lr + 64] = va1.y; As[lc + 2][lr + 64] = va1.z; As[lc + 3][lr + 64] = va1.w;
        Bs[lc + 0][lr] = vb0.x; Bs[lc + 1][lr] = vb0.y; Bs[lc + 2][lr] = vb0.z; Bs[lc + 3][lr] = vb0.w;
        Bs[lc + 0][lr + 64] = vb1.x; Bs[lc + 1][lr + 64] = vb1.y; Bs[lc + 2][lr + 64] = vb1.z; Bs[lc + 3][lr + 64] = vb1.w;
        __syncthreads();

#pragma unroll
        for (int kk = 0; kk < BK; kk++) {
            float a[8], b[8];
            *(float4*)&a[0] = *(const float4*)&As[kk][ty * 8];
            *(float4*)&a[4] = *(const float4*)&As[kk][ty * 8 + 4];
            *(float4*)&b[0] = *(const float4*)&Bs[kk][tx * 8];
            *(float4*)&b[4] = *(const float4*)&Bs[kk][tx * 8 + 4];
#pragma unroll
            for (int i = 0; i < 8; i++)
#pragma unroll
                for (int j = 0; j < 8; j++) acc[i][j] += a[i] * b[j];
        }
        __syncthreads();
    }

    float bias[8];
#pragma unroll
    for (int j = 0; j < 8; j++) {
        int n = n0 + tx * 8 + j;
        bias[j] = b1[n] + b2[n];
    }
#pragma unroll
    for (int i = 0; i < 8; i++) {
        int m = m0 + ty * 8 + i;
        int row = z ? (SN - 1 - m) : m;
        float* outr = &g_XI[z][row][n0 + tx * 8];
        float4 v0, v1;
        v0.x = acc[i][0] + bias[0]; v0.y = acc[i][1] + bias[1];
        v0.z = acc[i][2] + bias[2]; v0.w = acc[i][3] + bias[3];
        v1.x = acc[i][4] + bias[4]; v1.y = acc[i][5] + bias[5];
        v1.z = acc[i][6] + bias[6]; v1.w = acc[i][7] + bias[7];
        *(float4*)outr = v0;
        *(float4*)(outr + 4) = v1;
    }
}

// ---------------------------------------------------------------------------
// Kernel B: persistent BiLSTM recurrence — R12 structure exactly (R7 protocol,
// 5/3 register/smem weight split, block-synchronous gsum tail).
// Only change: gate transcendentals use HW tanh.approx (tanh + tanh-based
// sigmoid), shortening the serial publish tail by ~150 cyc/step.
// ---------------------------------------------------------------------------
#define NBLK 128
#define OPB  16
#define LSTM_SMEM ((24 * 1024 + 1024 + 64) * 4)

__global__ void __launch_bounds__(256, 1) lstm_kernel(
    const float* __restrict__ Whh_f, const float* __restrict__ Whh_b)
{
    extern __shared__ float sm[];
    float* wsh  = sm;                    // 24*1024 floats (smem-resident rows)
    float* hs   = sm + 24 * 1024;        // 1024 floats (h_prev)
    float* gsum = hs + 1024;             // 64 row sums

    const int tid  = threadIdx.x;
    const int w    = tid >> 5;
    const int lane = tid & 31;
    const int b    = blockIdx.x;
    const int dir  = b >> 6;
    const int jbase = (b & 63) * OPB;
    const float* Whh = dir ? Whh_b : Whh_f;

    // -------- load weights: rows 8w..8w+4 -> regs, 8w+5..8w+7 -> smem -------
    float4 wr[5][8];
#pragma unroll
    for (int q = 0; q < 5; q++) {
        int rr = 8 * w + q;
        int grow = (rr >> 4) * HN + jbase + (rr & 15);
        const float4* src = (const float4*)(Whh + (size_t)grow * HN);
#pragma unroll
        for (int m = 0; m < 8; m++) wr[q][m] = src[lane + 32 * m];
    }
#pragma unroll
    for (int q = 0; q < 3; q++) {
        int rr = 8 * w + 5 + q;
        int grow = (rr >> 4) * HN + jbase + (rr & 15);
        const float4* src = (const float4*)(Whh + (size_t)grow * HN);
        float4* dst = (float4*)(wsh + (size_t)(w * 3 + q) * HN);
#pragma unroll
        for (int m = 0; m < 8; m++) dst[lane + 32 * m] = src[lane + 32 * m];
    }

    float c_state = 0.0f;

    for (int t = 0; t < SN; t++) {
        // prefetch xi for this step (long-latency; hidden behind the poll)
        float xi0 = 0.f, xi1 = 0.f, xi2 = 0.f, xi3 = 0.f;
        if (tid < OPB) {
            const float* xr = &g_XI[dir][t][0];
            xi0 = __ldg(xr + 0 * HN + jbase + tid);
            xi1 = __ldg(xr + 1 * HN + jbase + tid);
            xi2 = __ldg(xr + 2 * HN + jbase + tid);
            xi3 = __ldg(xr + 3 * HN + jbase + tid);
        }

        // consume h_t: every thread polls its own 16B quad until valid,
        // then stages it straight into smem. Poll == load, no indirection.
        {
            const uint4* src = (const uint4*)&g_Hbuf[dir][t & 3][0] + tid;
            uint4 v;
            do {
                v = ldacq4(src);
            } while (v.x == POISON || v.y == POISON || v.z == POISON || v.w == POISON);
            ((uint4*)hs)[tid] = v;
        }
        __syncthreads();

        // poison our own chunk of slot (t+2)&3 (consumed; rewritten by us at
        // step t+1; release publish below orders this first).
        if (tid < OPB) {
            g_Hbuf[dir][(t + 2) & 3][jbase + tid] = __uint_as_float(POISON);
        }

        // h chunk into registers
        float4 hv[8];
#pragma unroll
        for (int m = 0; m < 8; m++) hv[m] = ((const float4*)hs)[lane + 32 * m];

        float acc[8];
#pragma unroll
        for (int r = 0; r < 8; r++) acc[r] = 0.0f;

        // register-resident rows (5)
#pragma unroll
        for (int q = 0; q < 5; q++) {
#pragma unroll
            for (int m = 0; m < 8; m++) {
                float4 ww = wr[q][m];
                acc[q] += ww.x * hv[m].x + ww.y * hv[m].y + ww.z * hv[m].z + ww.w * hv[m].w;
            }
        }
        // smem-resident rows (3)
#pragma unroll
        for (int q = 0; q < 3; q++) {
            const float4* wp = (const float4*)(wsh + (size_t)(w * 3 + q) * HN);
            float a = 0.0f;
#pragma unroll
            for (int m = 0; m < 8; m++) {
                float4 ww = wp[lane + 32 * m];
                a += ww.x * hv[m].x + ww.y * hv[m].y + ww.z * hv[m].z + ww.w * hv[m].w;
            }
            acc[5 + q] = a;
        }

        // warp reduction over K
#pragma unroll
        for (int r = 0; r < 8; r++) {
#pragma unroll
            for (int o = 16; o > 0; o >>= 1)
                acc[r] += __shfl_xor_sync(0xffffffffu, acc[r], o);
        }
        if (lane == 0) {
#pragma unroll
            for (int r = 0; r < 8; r++) gsum[8 * w + r] = acc[r];
        }
        __syncthreads();

        // gate assembly + cell update + publish h_{t+1} (coherent burst)
        // HW tanh path: 5 MUFU.TANH + FMAs, no exp, no divide.
        if (tid < OPB) {
            float gi = gsum[tid]          + xi0;
            float gf = gsum[16 + tid]     + xi1;
            float gg = gsum[32 + tid]     + xi2;
            float go = gsum[48 + tid]     + xi3;
            float si = sig_hw(gi);
            float sf = sig_hw(gf);
            float tg = tanh_hw(gg);
            float so = sig_hw(go);
            c_state = sf * c_state + si * tg;
            float hout = so * tanh_hw(c_state);
            int j = jbase + tid;
            strel_f(&g_Hbuf[dir][(t + 1) & 3][j], hout);
            int srow = dir ? (SN - 1 - t) : t;
            g_Hseq[dir][srow][j] = hout;
        }
    }
}

// ---------------------------------------------------------------------------
// Kernel C: feats = concat(hf, hb) @ W_dense^T + b_dense. 4 rows per block.
// ---------------------------------------------------------------------------
__global__ void __launch_bounds__(256) dense_kernel(
    const float* __restrict__ Wd, const float* __restrict__ bd)
{
    __shared__ float hsm[4][2 * HN];
    const int tid  = threadIdx.x;
    const int w    = tid >> 5;
    const int lane = tid & 31;
    const int s0   = blockIdx.x * 4;

    for (int i = tid; i < 4 * 512; i += 256) {
        int r = i >> 9, f4 = i & 511;
        float4 v;
        if (f4 < 256) v = *(const float4*)&g_Hseq[0][s0 + r][f4 * 4];
        else          v = *(const float4*)&g_Hseq[1][s0 + r][(f4 - 256) * 4];
        *(float4*)&hsm[r][f4 * 4] = v;
    }
    __syncthreads();

    for (int idx = w; idx < 4 * TN; idx += 8) {
        int r = idx / TN, tag = idx - r * TN;
        const float4* wrow = (const float4*)(Wd + (size_t)tag * 2 * HN);
        const float4* hrow = (const float4*)&hsm[r][0];
        float acc = 0.0f;
#pragma unroll
        for (int m = 0; m < 16; m++) {
            float4 a  = wrow[lane + 32 * m];
            float4 h4 = hrow[lane + 32 * m];
            acc += a.x * h4.x + a.y * h4.y + a.z * h4.z + a.w * h4.w;
        }
#pragma unroll
        for (int o = 16; o > 0; o >>= 1) acc += __shfl_xor_sync(0xffffffffu, acc, o);
        if (lane == 0) g_feats[(s0 + r) * TN + tag] = acc + __ldg(&bd[tag]);
    }
}

// ---------------------------------------------------------------------------
// Kernel D: Viterbi forward + chunked smem backtrack (validated).
// 2 threads per tag row, 4 compare chains each; first-max tie-break preserved.
// ---------------------------------------------------------------------------
__global__ void __launch_bounds__(128) viterbi_kernel(
    const float* __restrict__ trans, float* __restrict__ out, int out_size)
{
    __shared__ float fvb[2][TN];
    __shared__ unsigned char bpc[256 * TN];   // 12 KB backtrack chunk
    const int tid  = threadIdx.x;
    const int row  = tid >> 1;
    const int half = tid & 1;

    float tr[24];
    if (tid < 96) {
#pragma unroll
        for (int j = 0; j < 24; j++) tr[j] = __ldg(&trans[row * TN + half * 24 + j]);
    }
    if (tid < TN) fvb[0][tid] = (tid == START_TAG) ? 0.0f : NEGV;
    __syncthreads();

    for (int s = 0; s < SN; s++) {
        const float* fv = fvb[s & 1];
        float* fvn = fvb[(s + 1) & 1];
        if (tid < 96) {
            float feat = half ? 0.0f : __ldg(&g_feats[s * TN + row]);
            const int jb = half * 24;
            float b0 = fv[jb + 0]  + tr[0];  int a0 = jb + 0;
            float b1 = fv[jb + 6]  + tr[6];  int a1 = jb + 6;
            float b2 = fv[jb + 12] + tr[12]; int a2 = jb + 12;
            float b3 = fv[jb + 18] + tr[18]; int a3 = jb + 18;
#pragma unroll
            for (int k = 1; k < 6; k++) {
                float v0 = fv[jb + k]      + tr[k];      if (v0 > b0) { b0 = v0; a0 = jb + k; }
                float v1 = fv[jb + 6 + k]  + tr[6 + k];  if (v1 > b1) { b1 = v1; a1 = jb + 6 + k; }
                float v2 = fv[jb + 12 + k] + tr[12 + k]; if (v2 > b2) { b2 = v2; a2 = jb + 12 + k; }
                float v3 = fv[jb + 18 + k] + tr[18 + k]; if (v3 > b3) { b3 = v3; a3 = jb + 18 + k; }
            }
            if (b1 > b0) { b0 = b1; a0 = a1; }
            if (b3 > b2) { b2 = b3; a2 = a3; }
            if (b2 > b0) { b0 = b2; a0 = a2; }
            float bo = __shfl_xor_sync(0xffffffffu, b0, 1);
            int   ao = __shfl_xor_sync(0xffffffffu, a0, 1);
            if (half == 0) {
                if (bo > b0) { b0 = bo; a0 = ao; }  // other half's indices all larger
                fvn[row] = b0 + feat;
                g_bp[s * TN + row] = (unsigned char)a0;
            }
        }
        __syncthreads();
    }

    __shared__ int s_arg;
    if (tid == 0) {
        float best = -3.4e38f; int arg = 0;
        const float* fvf = fvb[SN & 1];
        for (int i = 0; i < TN; i++) {
            float v = fvf[i] + __ldg(&trans[END_TAG * TN + i]);
            if (v > best) { best = v; arg = i; }
        }
        if (out_size > 0) out[0] = best;
        if (SN < out_size) out[SN] = (float)arg;
        s_arg = arg;
    }
    __syncthreads();

    int cur = s_arg;  // live in tid 0 only
    for (int c0 = SN - 256; c0 >= 0; c0 -= 256) {
        const uint4* src = (const uint4*)&g_bp[c0 * TN];
        uint4* dst = (uint4*)bpc;
        for (int i = tid; i < 256 * TN / 16; i += 128) dst[i] = src[i];
        __syncthreads();
        if (tid == 0) {
            int hi = c0 + 255; if (hi > SN - 1) hi = SN - 1;
            int lo = (c0 > 0) ? c0 : 1;
            for (int s = hi; s >= lo; s--) {
                cur = bpc[(s - c0) * TN + cur];
                if (s < out_size) out[s] = (float)cur;
            }
        }
        __syncthreads();
    }
}

// ---------------------------------------------------------------------------
// Launch
// ---------------------------------------------------------------------------
extern "C" void kernel_launch(void* const* d_in, const int* in_sizes, int n_in,
                              void* d_out, int out_size)
{
    const float* sentence    = (const float*)d_in[0];
    const float* W_ih_f      = (const float*)d_in[1];
    const float* W_hh_f      = (const float*)d_in[2];
    const float* b_ih_f      = (const float*)d_in[3];
    const float* b_hh_f      = (const float*)d_in[4];
    const float* W_ih_b      = (const float*)d_in[5];
    const float* W_hh_b      = (const float*)d_in[6];
    const float* b_ih_b      = (const float*)d_in[7];
    const float* b_hh_b      = (const float*)d_in[8];
    const float* W_dense     = (const float*)d_in[9];
    const float* b_dense     = (const float*)d_in[10];
    const float* transitions = (const float*)d_in[11];
    float* out = (float*)d_out;

    (void)in_sizes; (void)n_in;

    cudaFuncSetAttribute(lstm_kernel, cudaFuncAttributeMaxDynamicSharedMemorySize, LSTM_SMEM);

    init_kernel<<<1, 256>>>();

    dim3 ggemm(4 * HN / BN, SN / BM, 2);
    xi_gemm_kernel<<<ggemm, 256>>>(sentence, W_ih_f, W_ih_b,
                                   b_ih_f, b_hh_f, b_ih_b, b_hh_b);

    spacer_kernel<<<1, 32>>>();   // keeps ncu's fixed skip landing on lstm

    lstm_kernel<<<NBLK, 256, LSTM_SMEM>>>(W_hh_f, W_hh_b);

    dense_kernel<<<SN / 4, 256>>>(W_dense, b_dense);

    viterbi_kernel<<<1, 128>>>(transitions, out, out_size);
}

// round 16
// speedup vs baseline: 1.1006x; 1.0240x over previous
#include <cuda_runtime.h>
#include <cuda_bf16.h>
#include <cstdint>
#include <cstddef>

// ---------------------------------------------------------------------------
// Problem constants
// ---------------------------------------------------------------------------
#define HN   1024
#define SN   8192
#define TN   48
#define START_TAG 46
#define END_TAG   47
#define NEGV (-10000.0f)
#define POISON 0x7fc0deadu   // NaN payload; o*tanh(c) can never produce it

// ---------------------------------------------------------------------------
// Scratch (device globals; no runtime allocation allowed)
// ---------------------------------------------------------------------------
__device__ float g_XI[2][SN][4 * HN];     // x@W_ih^T + biases (dir 1 in step order)
__device__ float g_Hseq[2][SN][HN];       // h sequences, dir 1 reversed to sentence order
__device__ float g_Hbuf[2][4][HN];        // [dir][slot][j]: 4-parity self-signaling h exchange
__device__ float g_feats[SN * TN];
__device__ unsigned char g_bp[SN * TN];
__device__ unsigned g_sink;               // spacer kernel sink

__device__ __forceinline__ uint4 ldacq4(const uint4* p) {
    uint4 v;
    asm volatile("ld.global.acquire.gpu.v4.u32 {%0,%1,%2,%3}, [%4];"
                 : "=r"(v.x), "=r"(v.y), "=r"(v.z), "=r"(v.w) : "l"(p));
    return v;
}
__device__ __forceinline__ void strel_f(float* p, float v) {
    asm volatile("st.global.release.gpu.b32 [%0], %1;"
                 :: "l"(p), "r"(__float_as_uint(v)) : "memory");
}
// HW tanh (sm_75+): MUFU-class, lat ~16, max abs err ~1e-5.
__device__ __forceinline__ float tanh_hw(float x) {
    float y; asm("tanh.approx.f32 %0, %1;" : "=f"(y) : "f"(x)); return y;
}
// sigmoid via HW tanh: sig(x) = 0.5*tanh(x/2) + 0.5
__device__ __forceinline__ float sig_hw(float x) {
    return fmaf(0.5f, tanh_hw(0.5f * x), 0.5f);
}

// ---------------------------------------------------------------------------
// Init: slot 0 = zeros (h0 = 0), slots 1..3 = poison. Runs every launch.
// ---------------------------------------------------------------------------
__global__ void init_kernel() {
    int tid = threadIdx.x;
    unsigned* hb = (unsigned*)&g_Hbuf[0][0][0];
    for (int i = tid; i < 2 * 4 * HN; i += blockDim.x) {
        int slot = (i / HN) & 3;
        hb[i] = (slot == 0) ? 0u : POISON;
    }
}

// Spacer: shifts launch-slot indexing so ncu's fixed skip lands on lstm_kernel.
__global__ void spacer_kernel() {
    if (threadIdx.x == 0) g_sink = 1u;
}

// ---------------------------------------------------------------------------
// Kernel A: XI = x @ W_ih^T + (b_ih + b_hh)  for both directions.
// Tiled SGEMM: BM=BN=128, BK=32 (halves barrier/refill events vs BK=16),
// 256 threads, 8x8 microtile, plain FFMA, single buffer.
// ---------------------------------------------------------------------------
#define BM 128
#define BN 128
#define BK 32

__global__ void __launch_bounds__(256) xi_gemm_kernel(
    const float* __restrict__ x,
    const float* __restrict__ Wf, const float* __restrict__ Wb,
    const float* __restrict__ bihf, const float* __restrict__ bhhf,
    const float* __restrict__ bihb, const float* __restrict__ bhhb)
{
    __shared__ float As[BK][BM + 4];
    __shared__ float Bs[BK][BN + 4];

    const int z  = blockIdx.z;
    const float* W  = z ? Wb   : Wf;
    const float* b1 = z ? bihb : bihf;
    const float* b2 = z ? bhhb : bhhf;

    const int m0 = blockIdx.y * BM;
    const int n0 = blockIdx.x * BN;
    const int tid = threadIdx.x;

    const int lr8 = tid >> 3;         // 0..31 (row within 32-row group)
    const int lc8 = (tid & 7) << 2;   // 0,4,...,28 (col quad within BK)
    const int ty  = tid >> 4;         // 0..15
    const int tx  = tid & 15;         // 0..15

    float acc[8][8];
#pragma unroll
    for (int i = 0; i < 8; i++)
#pragma unroll
        for (int j = 0; j < 8; j++) acc[i][j] = 0.0f;

    for (int k0 = 0; k0 < HN; k0 += BK) {
        // each thread loads 4 rows (stride 32) x 4 cols per matrix
#pragma unroll
        for (int r = 0; r < 4; r++) {
            int row = lr8 + 32 * r;
            float4 va = *(const float4*)&x[(size_t)(m0 + row) * HN + k0 + lc8];
            As[lc8 + 0][row] = va.x; As[lc8 + 1][row] = va.y;
            As[lc8 + 2][row] = va.z; As[lc8 + 3][row] = va.w;
            float4 vb = *(const float4*)&W[(size_t)(n0 + row) * HN + k0 + lc8];
            Bs[lc8 + 0][row] = vb.x; Bs[lc8 + 1][row] = vb.y;
            Bs[lc8 + 2][row] = vb.z; Bs[lc8 + 3][row] = vb.w;
        }
        __syncthreads();

#pragma unroll
        for (int kk = 0; kk < BK; kk++) {
            float a[8], b[8];
            *(float4*)&a[0] = *(const float4*)&As[kk][ty * 8];
            *(float4*)&a[4] = *(const float4*)&As[kk][ty * 8 + 4];
            *(float4*)&b[0] = *(const float4*)&Bs[kk][tx * 8];
            *(float4*)&b[4] = *(const float4*)&Bs[kk][tx * 8 + 4];
#pragma unroll
            for (int i = 0; i < 8; i++)
#pragma unroll
                for (int j = 0; j < 8; j++) acc[i][j] += a[i] * b[j];
        }
        __syncthreads();
    }

    float bias[8];
#pragma unroll
    for (int j = 0; j < 8; j++) {
        int n = n0 + tx * 8 + j;
        bias[j] = b1[n] + b2[n];
    }
#pragma unroll
    for (int i = 0; i < 8; i++) {
        int m = m0 + ty * 8 + i;
        int row = z ? (SN - 1 - m) : m;
        float* outr = &g_XI[z][row][n0 + tx * 8];
        float4 v0, v1;
        v0.x = acc[i][0] + bias[0]; v0.y = acc[i][1] + bias[1];
        v0.z = acc[i][2] + bias[2]; v0.w = acc[i][3] + bias[3];
        v1.x = acc[i][4] + bias[4]; v1.y = acc[i][5] + bias[5];
        v1.z = acc[i][6] + bias[6]; v1.w = acc[i][7] + bias[7];
        *(float4*)outr = v0;
        *(float4*)(outr + 4) = v1;
    }
}

// ---------------------------------------------------------------------------
// Kernel B: persistent BiLSTM recurrence — R15 exactly (R7 protocol, 5/3
// register/smem weight split, block-synchronous gsum tail, HW tanh gates).
// ---------------------------------------------------------------------------
#define NBLK 128
#define OPB  16
#define LSTM_SMEM ((24 * 1024 + 1024 + 64) * 4)

__global__ void __launch_bounds__(256, 1) lstm_kernel(
    const float* __restrict__ Whh_f, const float* __restrict__ Whh_b)
{
    extern __shared__ float sm[];
    float* wsh  = sm;                    // 24*1024 floats (smem-resident rows)
    float* hs   = sm + 24 * 1024;        // 1024 floats (h_prev)
    float* gsum = hs + 1024;             // 64 row sums

    const int tid  = threadIdx.x;
    const int w    = tid >> 5;
    const int lane = tid & 31;
    const int b    = blockIdx.x;
    const int dir  = b >> 6;
    const int jbase = (b & 63) * OPB;
    const float* Whh = dir ? Whh_b : Whh_f;

    // -------- load weights: rows 8w..8w+4 -> regs, 8w+5..8w+7 -> smem -------
    float4 wr[5][8];
#pragma unroll
    for (int q = 0; q < 5; q++) {
        int rr = 8 * w + q;
        int grow = (rr >> 4) * HN + jbase + (rr & 15);
        const float4* src = (const float4*)(Whh + (size_t)grow * HN);
#pragma unroll
        for (int m = 0; m < 8; m++) wr[q][m] = src[lane + 32 * m];
    }
#pragma unroll
    for (int q = 0; q < 3; q++) {
        int rr = 8 * w + 5 + q;
        int grow = (rr >> 4) * HN + jbase + (rr & 15);
        const float4* src = (const float4*)(Whh + (size_t)grow * HN);
        float4* dst = (float4*)(wsh + (size_t)(w * 3 + q) * HN);
#pragma unroll
        for (int m = 0; m < 8; m++) dst[lane + 32 * m] = src[lane + 32 * m];
    }

    float c_state = 0.0f;

    for (int t = 0; t < SN; t++) {
        // prefetch xi for this step (long-latency; hidden behind the poll)
        float xi0 = 0.f, xi1 = 0.f, xi2 = 0.f, xi3 = 0.f;
        if (tid < OPB) {
            const float* xr = &g_XI[dir][t][0];
            xi0 = __ldg(xr + 0 * HN + jbase + tid);
            xi1 = __ldg(xr + 1 * HN + jbase + tid);
            xi2 = __ldg(xr + 2 * HN + jbase + tid);
            xi3 = __ldg(xr + 3 * HN + jbase + tid);
        }

        // consume h_t: every thread polls its own 16B quad until valid,
        // then stages it straight into smem. Poll == load, no indirection.
        {
            const uint4* src = (const uint4*)&g_Hbuf[dir][t & 3][0] + tid;
            uint4 v;
            do {
                v = ldacq4(src);
            } while (v.x == POISON || v.y == POISON || v.z == POISON || v.w == POISON);
            ((uint4*)hs)[tid] = v;
        }
        __syncthreads();

        // poison our own chunk of slot (t+2)&3 (consumed; rewritten by us at
        // step t+1; release publish below orders this first).
        if (tid < OPB) {
            g_Hbuf[dir][(t + 2) & 3][jbase + tid] = __uint_as_float(POISON);
        }

        // h chunk into registers
        float4 hv[8];
#pragma unroll
        for (int m = 0; m < 8; m++) hv[m] = ((const float4*)hs)[lane + 32 * m];

        float acc[8];
#pragma unroll
        for (int r = 0; r < 8; r++) acc[r] = 0.0f;

        // register-resident rows (5)
#pragma unroll
        for (int q = 0; q < 5; q++) {
#pragma unroll
            for (int m = 0; m < 8; m++) {
                float4 ww = wr[q][m];
                acc[q] += ww.x * hv[m].x + ww.y * hv[m].y + ww.z * hv[m].z + ww.w * hv[m].w;
            }
        }
        // smem-resident rows (3)
#pragma unroll
        for (int q = 0; q < 3; q++) {
            const float4* wp = (const float4*)(wsh + (size_t)(w * 3 + q) * HN);
            float a = 0.0f;
#pragma unroll
            for (int m = 0; m < 8; m++) {
                float4 ww = wp[lane + 32 * m];
                a += ww.x * hv[m].x + ww.y * hv[m].y + ww.z * hv[m].z + ww.w * hv[m].w;
            }
            acc[5 + q] = a;
        }

        // warp reduction over K
#pragma unroll
        for (int r = 0; r < 8; r++) {
#pragma unroll
            for (int o = 16; o > 0; o >>= 1)
                acc[r] += __shfl_xor_sync(0xffffffffu, acc[r], o);
        }
        if (lane == 0) {
#pragma unroll
            for (int r = 0; r < 8; r++) gsum[8 * w + r] = acc[r];
        }
        __syncthreads();

        // gate assembly + cell update + publish h_{t+1} (coherent burst)
        if (tid < OPB) {
            float gi = gsum[tid]          + xi0;
            float gf = gsum[16 + tid]     + xi1;
            float gg = gsum[32 + tid]     + xi2;
            float go = gsum[48 + tid]     + xi3;
            float si = sig_hw(gi);
            float sf = sig_hw(gf);
            float tg = tanh_hw(gg);
            float so = sig_hw(go);
            c_state = sf * c_state + si * tg;
            float hout = so * tanh_hw(c_state);
            int j = jbase + tid;
            strel_f(&g_Hbuf[dir][(t + 1) & 3][j], hout);
            int srow = dir ? (SN - 1 - t) : t;
            g_Hseq[dir][srow][j] = hout;
        }
    }
}

// ---------------------------------------------------------------------------
// Kernel C: feats = concat(hf, hb) @ W_dense^T + b_dense. 4 rows per block.
// ---------------------------------------------------------------------------
__global__ void __launch_bounds__(256) dense_kernel(
    const float* __restrict__ Wd, const float* __restrict__ bd)
{
    __shared__ float hsm[4][2 * HN];
    const int tid  = threadIdx.x;
    const int w    = tid >> 5;
    const int lane = tid & 31;
    const int s0   = blockIdx.x * 4;

    for (int i = tid; i < 4 * 512; i += 256) {
        int r = i >> 9, f4 = i & 511;
        float4 v;
        if (f4 < 256) v = *(const float4*)&g_Hseq[0][s0 + r][f4 * 4];
        else          v = *(const float4*)&g_Hseq[1][s0 + r][(f4 - 256) * 4];
        *(float4*)&hsm[r][f4 * 4] = v;
    }
    __syncthreads();

    for (int idx = w; idx < 4 * TN; idx += 8) {
        int r = idx / TN, tag = idx - r * TN;
        const float4* wrow = (const float4*)(Wd + (size_t)tag * 2 * HN);
        const float4* hrow = (const float4*)&hsm[r][0];
        float acc = 0.0f;
#pragma unroll
        for (int m = 0; m < 16; m++) {
            float4 a  = wrow[lane + 32 * m];
            float4 h4 = hrow[lane + 32 * m];
            acc += a.x * h4.x + a.y * h4.y + a.z * h4.z + a.w * h4.w;
        }
#pragma unroll
        for (int o = 16; o > 0; o >>= 1) acc += __shfl_xor_sync(0xffffffffu, acc, o);
        if (lane == 0) g_feats[(s0 + r) * TN + tag] = acc + __ldg(&bd[tag]);
    }
}

// ---------------------------------------------------------------------------
// Kernel D: Viterbi forward + chunked smem backtrack.
// NOW with feat software-pipelining: feat[s+1] is loaded while step s's
// 48-way max relaxation runs, hiding the ~250-cycle L2 load each step.
// First-max tie-break preserved.
// ---------------------------------------------------------------------------
__global__ void __launch_bounds__(128) viterbi_kernel(
    const float* __restrict__ trans, float* __restrict__ out, int out_size)
{
    __shared__ float fvb[2][TN];
    __shared__ unsigned char bpc[256 * TN];   // 12 KB backtrack chunk
    const int tid  = threadIdx.x;
    const int row  = tid >> 1;
    const int half = tid & 1;
    const bool leader = (tid < 96) && (half == 0);

    float tr[24];
    if (tid < 96) {
#pragma unroll
        for (int j = 0; j < 24; j++) tr[j] = __ldg(&trans[row * TN + half * 24 + j]);
    }
    if (tid < TN) fvb[0][tid] = (tid == START_TAG) ? 0.0f : NEGV;
    __syncthreads();

    float featc = leader ? __ldg(&g_feats[row]) : 0.0f;   // feat for s=0

    for (int s = 0; s < SN; s++) {
        // prefetch next step's feat (consumed after the relaxation below)
        float featn = 0.0f;
        if (leader && (s + 1) < SN) featn = __ldg(&g_feats[(s + 1) * TN + row]);

        const float* fv = fvb[s & 1];
        float* fvn = fvb[(s + 1) & 1];
        if (tid < 96) {
            const int jb = half * 24;
            float b0 = fv[jb + 0]  + tr[0];  int a0 = jb + 0;
            float b1 = fv[jb + 6]  + tr[6];  int a1 = jb + 6;
            float b2 = fv[jb + 12] + tr[12]; int a2 = jb + 12;
            float b3 = fv[jb + 18] + tr[18]; int a3 = jb + 18;
#pragma unroll
            for (int k = 1; k < 6; k++) {
                float v0 = fv[jb + k]      + tr[k];      if (v0 > b0) { b0 = v0; a0 = jb + k; }
                float v1 = fv[jb + 6 + k]  + tr[6 + k];  if (v1 > b1) { b1 = v1; a1 = jb + 6 + k; }
                float v2 = fv[jb + 12 + k] + tr[12 + k]; if (v2 > b2) { b2 = v2; a2 = jb + 12 + k; }
                float v3 = fv[jb + 18 + k] + tr[18 + k]; if (v3 > b3) { b3 = v3; a3 = jb + 18 + k; }
            }
            if (b1 > b0) { b0 = b1; a0 = a1; }
            if (b3 > b2) { b2 = b3; a2 = a3; }
            if (b2 > b0) { b0 = b2; a0 = a2; }
            float bo = __shfl_xor_sync(0xffffffffu, b0, 1);
            int   ao = __shfl_xor_sync(0xffffffffu, a0, 1);
            if (half == 0) {
                if (bo > b0) { b0 = bo; a0 = ao; }  // other half's indices all larger
                fvn[row] = b0 + featc;
                g_bp[s * TN + row] = (unsigned char)a0;
            }
        }
        featc = featn;
        __syncthreads();
    }

    __shared__ int s_arg;
    if (tid == 0) {
        float best = -3.4e38f; int arg = 0;
        const float* fvf = fvb[SN & 1];
        for (int i = 0; i < TN; i++) {
            float v = fvf[i] + __ldg(&trans[END_TAG * TN + i]);
            if (v > best) { best = v; arg = i; }
        }
        if (out_size > 0) out[0] = best;
        if (SN < out_size) out[SN] = (float)arg;
        s_arg = arg;
    }
    __syncthreads();

    int cur = s_arg;  // live in tid 0 only
    for (int c0 = SN - 256; c0 >= 0; c0 -= 256) {
        const uint4* src = (const uint4*)&g_bp[c0 * TN];
        uint4* dst = (uint4*)bpc;
        for (int i = tid; i < 256 * TN / 16; i += 128) dst[i] = src[i];
        __syncthreads();
        if (tid == 0) {
            int hi = c0 + 255; if (hi > SN - 1) hi = SN - 1;
            int lo = (c0 > 0) ? c0 : 1;
            for (int s = hi; s >= lo; s--) {
                cur = bpc[(s - c0) * TN + cur];
                if (s < out_size) out[s] = (float)cur;
            }
        }
        __syncthreads();
    }
}

// ---------------------------------------------------------------------------
// Launch
// ---------------------------------------------------------------------------
extern "C" void kernel_launch(void* const* d_in, const int* in_sizes, int n_in,
                              void* d_out, int out_size)
{
    const float* sentence    = (const float*)d_in[0];
    const float* W_ih_f      = (const float*)d_in[1];
    const float* W_hh_f      = (const float*)d_in[2];
    const float* b_ih_f      = (const float*)d_in[3];
    const float* b_hh_f      = (const float*)d_in[4];
    const float* W_ih_b      = (const float*)d_in[5];
    const float* W_hh_b      = (const float*)d_in[6];
    const float* b_ih_b      = (const float*)d_in[7];
    const float* b_hh_b      = (const float*)d_in[8];
    const float* W_dense     = (const float*)d_in[9];
    const float* b_dense     = (const float*)d_in[10];
    const float* transitions = (const float*)d_in[11];
    float* out = (float*)d_out;

    (void)in_sizes; (void)n_in;

    cudaFuncSetAttribute(lstm_kernel, cudaFuncAttributeMaxDynamicSharedMemorySize, LSTM_SMEM);

    init_kernel<<<1, 256>>>();

    dim3 ggemm(4 * HN / BN, SN / BM, 2);
    xi_gemm_kernel<<<ggemm, 256>>>(sentence, W_ih_f, W_ih_b,
                                   b_ih_f, b_hh_f, b_ih_b, b_hh_b);

    spacer_kernel<<<1, 32>>>();   // keeps ncu's fixed skip landing on lstm

    lstm_kernel<<<NBLK, 256, LSTM_SMEM>>>(W_hh_f, W_hh_b);

    dense_kernel<<<SN / 4, 256>>>(W_dense, b_dense);

    viterbi_kernel<<<1, 128>>>(transitions, out, out_size);
}